// round 3
// baseline (speedup 1.0000x reference)
#include <cuda_runtime.h>
#include <cuda_fp16.h>
#include <cstdint>

// ============================ problem constants ============================
#define BATCHN   2097152
#define IN_DIMS  32
#define HIDDEN   64
#define OUTD     3
#define NMAT     5                 // W0 + 4 hidden (all followed by ReLU)
#define NTHREADS 256               // 8 warps
#define ROWS_PER_WARP 32           // 2 rowsets of 16
#define ROWS_PER_CTA  (8 * ROWS_PER_WARP)   // 256
#define NTILES   (BATCHN / ROWS_PER_CTA)    // 8192

// ============================ SMEM layout ============================
// pkw[l][s][n][t] : uint2 = the exact {b0,b1} register pair thread (g,t) needs
// for mma.m16n8k16 with B = W[k, n] (col n = jb*8+g, k-step s):
//   .x = f16x2{ W[s*16+2t, n],   W[s*16+2t+1, n] }
//   .y = f16x2{ W[s*16+2t+8, n], W[s*16+2t+9, n] }
// One LDS.64 per B fragment; banks (8g+2t) form a perfect permutation within
// each 16-lane phase -> conflict-free.
struct Smem {
    uint2  pkw[NMAT][4][64][4];   // 40960 B
    float2 wop[4][8][3];          // 768 B : {Wo[k0,j], Wo[k0+1,j]}, k0=jb*8+2t
};

// ============================ device helpers ============================
__device__ __forceinline__ void mma16816(float* d,
    uint32_t a0, uint32_t a1, uint32_t a2, uint32_t a3,
    uint32_t b0, uint32_t b1)
{
    asm volatile(
        "mma.sync.aligned.m16n8k16.row.col.f32.f16.f16.f32 "
        "{%0,%1,%2,%3}, {%4,%5,%6,%7}, {%8,%9}, {%0,%1,%2,%3};"
        : "+f"(d[0]), "+f"(d[1]), "+f"(d[2]), "+f"(d[3])
        : "r"(a0), "r"(a1), "r"(a2), "r"(a3), "r"(b0), "r"(b1));
}

// pack two f32 -> f16x2 (first arg = low half)
__device__ __forceinline__ uint32_t pack2(float lo, float hi) {
    uint32_t r;
    asm("cvt.rn.f16x2.f32 %0, %1, %2;" : "=r"(r) : "f"(hi), "f"(lo));
    return r;
}
__device__ __forceinline__ uint32_t packrelu(float lo, float hi) {
    return pack2(fmaxf(lo, 0.0f), fmaxf(hi, 0.0f));
}

// ============================ kernel ============================
__global__ void __launch_bounds__(NTHREADS, 2)
tcnn_mlp_kernel(const float* __restrict__ x,
                const float* __restrict__ W0,
                const float* __restrict__ Wh,
                const float* __restrict__ Wo,
                float* __restrict__ out)
{
    __shared__ Smem s;
    const int tid  = threadIdx.x;
    const int warp = tid >> 5;
    const int lane = tid & 31;
    const int g    = lane >> 2;   // groupID
    const int t    = lane & 3;    // threadID in group

    // ---- stage weights once per persistent CTA ----
    for (int idx = tid; idx < NMAT * 4 * 64 * 4; idx += NTHREADS) {
        int l   = idx >> 10;           // /1024
        int rem = idx & 1023;
        int ss  = rem >> 8;
        int n   = (rem >> 2) & 63;
        int tt  = rem & 3;
        int k0  = ss * 16 + tt * 2;
        float w0, w1, w2, w3;
        if (l == 0) {
            w0 = (k0     < IN_DIMS) ? W0[(k0    ) * HIDDEN + n] : 0.0f;
            w1 = (k0 + 1 < IN_DIMS) ? W0[(k0 + 1) * HIDDEN + n] : 0.0f;
            w2 = (k0 + 8 < IN_DIMS) ? W0[(k0 + 8) * HIDDEN + n] : 0.0f;
            w3 = (k0 + 9 < IN_DIMS) ? W0[(k0 + 9) * HIDDEN + n] : 0.0f;
        } else {
            const float* W = Wh + (size_t)(l - 1) * HIDDEN * HIDDEN;
            w0 = W[(k0    ) * HIDDEN + n];
            w1 = W[(k0 + 1) * HIDDEN + n];
            w2 = W[(k0 + 8) * HIDDEN + n];
            w3 = W[(k0 + 9) * HIDDEN + n];
        }
        __half2 p0 = __floats2half2_rn(w0, w1);
        __half2 p1 = __floats2half2_rn(w2, w3);
        uint2 v;
        v.x = *reinterpret_cast<uint32_t*>(&p0);
        v.y = *reinterpret_cast<uint32_t*>(&p1);
        s.pkw[l][ss][n][tt] = v;
    }
    for (int idx = tid; idx < 4 * 8 * 3; idx += NTHREADS) {
        int tt = idx / 24;
        int jb = (idx / 3) & 7;
        int j  = idx % 3;
        int k0 = jb * 8 + tt * 2;
        s.wop[tt][jb][j] = make_float2(Wo[k0 * OUTD + j], Wo[(k0 + 1) * OUTD + j]);
    }
    __syncthreads();

    // ---- persistent grid-stride over 256-row tiles ----
    for (int tile = blockIdx.x; tile < NTILES; tile += gridDim.x) {
        const size_t rbase = (size_t)tile * ROWS_PER_CTA + (size_t)warp * ROWS_PER_WARP;

        float acc[2][8][4];          // [rowset][n-block][c-frag]
        uint32_t af[2][4][4];        // [rowset][k-step][a-frag]

        // ---- layer 0: A fragments straight from gmem (K=32 -> 2 k-steps) ----
        #pragma unroll
        for (int r = 0; r < 2; ++r) {
            const float* xr0 = x + (rbase + (size_t)r * 16 + g) * IN_DIMS;
            const float* xr1 = xr0 + 8 * IN_DIMS;
            #pragma unroll
            for (int ss = 0; ss < 2; ++ss) {
                float2 v00 = *reinterpret_cast<const float2*>(xr0 + ss * 16 + 2 * t);
                float2 v01 = *reinterpret_cast<const float2*>(xr0 + ss * 16 + 2 * t + 8);
                float2 v10 = *reinterpret_cast<const float2*>(xr1 + ss * 16 + 2 * t);
                float2 v11 = *reinterpret_cast<const float2*>(xr1 + ss * 16 + 2 * t + 8);
                af[r][ss][0] = pack2(v00.x, v00.y);
                af[r][ss][1] = pack2(v10.x, v10.y);
                af[r][ss][2] = pack2(v01.x, v01.y);
                af[r][ss][3] = pack2(v11.x, v11.y);
            }
        }
        #pragma unroll
        for (int r = 0; r < 2; ++r)
            #pragma unroll
            for (int jb = 0; jb < 8; ++jb)
                #pragma unroll
                for (int c = 0; c < 4; ++c)
                    acc[r][jb][c] = 0.0f;

        #pragma unroll
        for (int jb = 0; jb < 8; ++jb) {
            #pragma unroll
            for (int ss = 0; ss < 2; ++ss) {
                uint2 b = s.pkw[0][ss][jb * 8 + g][t];
                mma16816(acc[0][jb], af[0][ss][0], af[0][ss][1], af[0][ss][2], af[0][ss][3], b.x, b.y);
                mma16816(acc[1][jb], af[1][ss][0], af[1][ss][1], af[1][ss][2], af[1][ss][3], b.x, b.y);
            }
        }

        // ---- hidden layers 1..4: acc -> ReLU/f16 -> A-frags -> mma ----
        #pragma unroll
        for (int l = 1; l < NMAT; ++l) {
            #pragma unroll
            for (int r = 0; r < 2; ++r) {
                #pragma unroll
                for (int ss = 0; ss < 4; ++ss) {
                    af[r][ss][0] = packrelu(acc[r][2 * ss    ][0], acc[r][2 * ss    ][1]);
                    af[r][ss][1] = packrelu(acc[r][2 * ss    ][2], acc[r][2 * ss    ][3]);
                    af[r][ss][2] = packrelu(acc[r][2 * ss + 1][0], acc[r][2 * ss + 1][1]);
                    af[r][ss][3] = packrelu(acc[r][2 * ss + 1][2], acc[r][2 * ss + 1][3]);
                }
            }
            #pragma unroll
            for (int r = 0; r < 2; ++r)
                #pragma unroll
                for (int jb = 0; jb < 8; ++jb)
                    #pragma unroll
                    for (int c = 0; c < 4; ++c)
                        acc[r][jb][c] = 0.0f;

            #pragma unroll
            for (int jb = 0; jb < 8; ++jb) {
                #pragma unroll
                for (int ss = 0; ss < 4; ++ss) {
                    uint2 b = s.pkw[l][ss][jb * 8 + g][t];
                    mma16816(acc[0][jb], af[0][ss][0], af[0][ss][1], af[0][ss][2], af[0][ss][3], b.x, b.y);
                    mma16816(acc[1][jb], af[1][ss][0], af[1][ss][1], af[1][ss][2], af[1][ss][3], b.x, b.y);
                }
            }
        }

        // ---- output layer: ReLU(h) @ Wo, quad reduction, write 3 f32/row ----
        #pragma unroll
        for (int r = 0; r < 2; ++r) {
            float p0[3] = {0.f, 0.f, 0.f};
            float p1[3] = {0.f, 0.f, 0.f};
            #pragma unroll
            for (int jb = 0; jb < 8; ++jb) {
                float h0 = fmaxf(acc[r][jb][0], 0.0f);
                float h1 = fmaxf(acc[r][jb][1], 0.0f);
                float h2 = fmaxf(acc[r][jb][2], 0.0f);
                float h3 = fmaxf(acc[r][jb][3], 0.0f);
                #pragma unroll
                for (int j = 0; j < 3; ++j) {
                    float2 w = s.wop[t][jb][j];
                    p0[j] = fmaf(h0, w.x, fmaf(h1, w.y, p0[j]));
                    p1[j] = fmaf(h2, w.x, fmaf(h3, w.y, p1[j]));
                }
            }
            #pragma unroll
            for (int j = 0; j < 3; ++j) {
                p0[j] += __shfl_xor_sync(0xffffffffu, p0[j], 1);
                p0[j] += __shfl_xor_sync(0xffffffffu, p0[j], 2);
                p1[j] += __shfl_xor_sync(0xffffffffu, p1[j], 1);
                p1[j] += __shfl_xor_sync(0xffffffffu, p1[j], 2);
            }
            if (t == 0) {
                size_t r0 = rbase + (size_t)r * 16 + g;
                size_t r1 = r0 + 8;
                float* o0 = out + r0 * OUTD;
                float* o1 = out + r1 * OUTD;
                o0[0] = p0[0]; o0[1] = p0[1]; o0[2] = p0[2];
                o1[0] = p1[0]; o1[1] = p1[1]; o1[2] = p1[2];
            }
        }
    }
}

extern "C" void kernel_launch(void* const* d_in, const int* in_sizes, int n_in,
                              void* d_out, int out_size) {
    const float* x  = (const float*)d_in[0];
    const float* W0 = (const float*)d_in[1];
    const float* Wh = (const float*)d_in[2];
    const float* Wo = (const float*)d_in[3];
    float* out = (float*)d_out;

    int sms = 148;
    cudaDeviceGetAttribute(&sms, cudaDevAttrMultiProcessorCount, 0);
    int grid = sms * 2;                 // persistent, 2 CTAs/SM
    if (grid > NTILES) grid = NTILES;

    tcnn_mlp_kernel<<<grid, NTHREADS>>>(x, W0, Wh, Wo, out);
}

// round 4
// speedup vs baseline: 1.6657x; 1.6657x over previous
#include <cuda_runtime.h>
#include <cuda_fp16.h>
#include <cstdint>

// ============================ problem constants ============================
#define BATCHN   2097152
#define IN_DIMS  32
#define HIDDEN   64
#define OUTD     3
#define NMAT     5                 // W0 + 4 hidden (all followed by ReLU)
#define NTHREADS 256               // 8 warps
#define ROWS_PER_WARP 32           // 2 rowsets of 16
#define ROWS_PER_CTA  (8 * ROWS_PER_WARP)   // 256
#define NTILES   (BATCHN / ROWS_PER_CTA)    // 8192

// ============================ SMEM layout ============================
// pkw[l][p][n][t] : uint4 = B fragments for k-step pair p = {ss=2p, ss=2p+1}
// for thread (g,t), column n = jb*8+g:
//   .x = f16x2{ W[32p+2t,    n], W[32p+2t+1,  n] }   (b0 of ss=2p)
//   .y = f16x2{ W[32p+2t+8,  n], W[32p+2t+9,  n] }   (b1 of ss=2p)
//   .z = f16x2{ W[32p+2t+16, n], W[32p+2t+17, n] }   (b0 of ss=2p+1)
//   .w = f16x2{ W[32p+2t+24, n], W[32p+2t+25, n] }   (b1 of ss=2p+1)
// One LDS.128 per (jb, k-step-pair); for fixed jb, lanes (g,t) cover a
// contiguous 512B block in 16B steps -> 4 phases x 128B, conflict-free.
struct Smem {
    uint4  pkw[NMAT][2][64][4];   // 40960 B
    float2 wop[4][8][3];          // 768 B : {Wo[k0,j], Wo[k0+1,j]}, k0=jb*8+2t
};

// ============================ device helpers ============================
__device__ __forceinline__ void mma16816(float* d,
    uint32_t a0, uint32_t a1, uint32_t a2, uint32_t a3,
    uint32_t b0, uint32_t b1)
{
    asm volatile(
        "mma.sync.aligned.m16n8k16.row.col.f32.f16.f16.f32 "
        "{%0,%1,%2,%3}, {%4,%5,%6,%7}, {%8,%9}, {%0,%1,%2,%3};"
        : "+f"(d[0]), "+f"(d[1]), "+f"(d[2]), "+f"(d[3])
        : "r"(a0), "r"(a1), "r"(a2), "r"(a3), "r"(b0), "r"(b1));
}

// D = A*B + 0  (no accumulator zero-init needed)
__device__ __forceinline__ void mma16816_zc(float* d,
    uint32_t a0, uint32_t a1, uint32_t a2, uint32_t a3,
    uint32_t b0, uint32_t b1)
{
    asm volatile(
        "mma.sync.aligned.m16n8k16.row.col.f32.f16.f16.f32 "
        "{%0,%1,%2,%3}, {%4,%5,%6,%7}, {%8,%9}, {%10,%11,%12,%13};"
        : "=f"(d[0]), "=f"(d[1]), "=f"(d[2]), "=f"(d[3])
        : "r"(a0), "r"(a1), "r"(a2), "r"(a3), "r"(b0), "r"(b1),
          "f"(0.0f), "f"(0.0f), "f"(0.0f), "f"(0.0f));
}

// pack two f32 -> f16x2 (first arg = low half)
__device__ __forceinline__ uint32_t pack2(float lo, float hi) {
    uint32_t r;
    asm("cvt.rn.f16x2.f32 %0, %1, %2;" : "=r"(r) : "f"(hi), "f"(lo));
    return r;
}
// fused relu+pack: single cvt.rn.relu.f16x2.f32 (base PTX, sm_80+)
__device__ __forceinline__ uint32_t packrelu(float lo, float hi) {
    uint32_t r;
    asm("cvt.rn.relu.f16x2.f32 %0, %1, %2;" : "=r"(r) : "f"(hi), "f"(lo));
    return r;
}

// ============================ kernel ============================
__global__ void __launch_bounds__(NTHREADS, 2)
tcnn_mlp_kernel(const float* __restrict__ x,
                const float* __restrict__ W0,
                const float* __restrict__ Wh,
                const float* __restrict__ Wo,
                float* __restrict__ out)
{
    __shared__ Smem s;
    const int tid  = threadIdx.x;
    const int warp = tid >> 5;
    const int lane = tid & 31;
    const int g    = lane >> 2;   // groupID
    const int t    = lane & 3;    // threadID in group

    // ---- stage weights once per persistent CTA ----
    for (int idx = tid; idx < NMAT * 2 * 64 * 4; idx += NTHREADS) {
        int l   = idx >> 9;            // /512
        int rem = idx & 511;
        int p   = rem >> 8;
        int n   = (rem >> 2) & 63;
        int tt  = rem & 3;
        int K0  = p * 32 + 2 * tt;
        const float* W = (l == 0) ? W0 : (Wh + (size_t)(l - 1) * HIDDEN * HIDDEN);
        float w[8];
        #pragma unroll
        for (int i = 0; i < 8; ++i) {
            int k = K0 + (i >> 1) * 8 + (i & 1);   // +0,+1,+8,+9,+16,+17,+24,+25
            float v = 0.0f;
            if (l != 0 || k < IN_DIMS) v = W[k * HIDDEN + n];
            w[i] = v;
        }
        uint4 v4;
        v4.x = pack2(w[0], w[1]);
        v4.y = pack2(w[2], w[3]);
        v4.z = pack2(w[4], w[5]);
        v4.w = pack2(w[6], w[7]);
        s.pkw[l][p][n][tt] = v4;
    }
    for (int idx = tid; idx < 4 * 8 * 3; idx += NTHREADS) {
        int tt = idx / 24;
        int jb = (idx / 3) & 7;
        int j  = idx % 3;
        int k0 = jb * 8 + tt * 2;
        s.wop[tt][jb][j] = make_float2(Wo[k0 * OUTD + j], Wo[(k0 + 1) * OUTD + j]);
    }
    __syncthreads();

    // ---- persistent grid-stride over 256-row tiles ----
    for (int tile = blockIdx.x; tile < NTILES; tile += gridDim.x) {
        const size_t rbase = (size_t)tile * ROWS_PER_CTA + (size_t)warp * ROWS_PER_WARP;

        float acc[2][8][4];          // [rowset][n-block][c-frag]
        uint32_t af[2][4][4];        // [rowset][k-step][a-frag]

        // ---- layer 0: A fragments straight from gmem (K=32 -> k-steps 0,1) ----
        #pragma unroll
        for (int r = 0; r < 2; ++r) {
            const float* xr0 = x + (rbase + (size_t)r * 16 + g) * IN_DIMS;
            const float* xr1 = xr0 + 8 * IN_DIMS;
            #pragma unroll
            for (int ss = 0; ss < 2; ++ss) {
                float2 v00 = *reinterpret_cast<const float2*>(xr0 + ss * 16 + 2 * t);
                float2 v01 = *reinterpret_cast<const float2*>(xr0 + ss * 16 + 2 * t + 8);
                float2 v10 = *reinterpret_cast<const float2*>(xr1 + ss * 16 + 2 * t);
                float2 v11 = *reinterpret_cast<const float2*>(xr1 + ss * 16 + 2 * t + 8);
                af[r][ss][0] = pack2(v00.x, v00.y);
                af[r][ss][1] = pack2(v10.x, v10.y);
                af[r][ss][2] = pack2(v01.x, v01.y);
                af[r][ss][3] = pack2(v11.x, v11.y);
            }
        }

        // layer 0 mma: k-step pair p=0 only (ss 0,1), first k-step uses C=0
        #pragma unroll
        for (int jbg = 0; jbg < 8; jbg += 4) {
            uint4 b[4];
            #pragma unroll
            for (int j = 0; j < 4; ++j)
                b[j] = s.pkw[0][0][(jbg + j) * 8 + g][t];
            #pragma unroll
            for (int j = 0; j < 4; ++j) {
                mma16816_zc(acc[0][jbg + j], af[0][0][0], af[0][0][1], af[0][0][2], af[0][0][3], b[j].x, b[j].y);
                mma16816_zc(acc[1][jbg + j], af[1][0][0], af[1][0][1], af[1][0][2], af[1][0][3], b[j].x, b[j].y);
            }
            #pragma unroll
            for (int j = 0; j < 4; ++j) {
                mma16816(acc[0][jbg + j], af[0][1][0], af[0][1][1], af[0][1][2], af[0][1][3], b[j].z, b[j].w);
                mma16816(acc[1][jbg + j], af[1][1][0], af[1][1][1], af[1][1][2], af[1][1][3], b[j].z, b[j].w);
            }
        }

        // ---- hidden layers 1..4: acc -> fused relu+pack -> A-frags -> mma ----
        #pragma unroll
        for (int l = 1; l < NMAT; ++l) {
            #pragma unroll
            for (int r = 0; r < 2; ++r) {
                #pragma unroll
                for (int ss = 0; ss < 4; ++ss) {
                    af[r][ss][0] = packrelu(acc[r][2 * ss    ][0], acc[r][2 * ss    ][1]);
                    af[r][ss][1] = packrelu(acc[r][2 * ss    ][2], acc[r][2 * ss    ][3]);
                    af[r][ss][2] = packrelu(acc[r][2 * ss + 1][0], acc[r][2 * ss + 1][1]);
                    af[r][ss][3] = packrelu(acc[r][2 * ss + 1][2], acc[r][2 * ss + 1][3]);
                }
            }
            #pragma unroll
            for (int p = 0; p < 2; ++p) {
                #pragma unroll
                for (int jbg = 0; jbg < 8; jbg += 4) {
                    uint4 b[4];
                    #pragma unroll
                    for (int j = 0; j < 4; ++j)
                        b[j] = s.pkw[l][p][(jbg + j) * 8 + g][t];
                    #pragma unroll
                    for (int j = 0; j < 4; ++j) {
                        if (p == 0) {
                            mma16816_zc(acc[0][jbg + j], af[0][0][0], af[0][0][1], af[0][0][2], af[0][0][3], b[j].x, b[j].y);
                            mma16816_zc(acc[1][jbg + j], af[1][0][0], af[1][0][1], af[1][0][2], af[1][0][3], b[j].x, b[j].y);
                        } else {
                            mma16816(acc[0][jbg + j], af[0][2][0], af[0][2][1], af[0][2][2], af[0][2][3], b[j].x, b[j].y);
                            mma16816(acc[1][jbg + j], af[1][2][0], af[1][2][1], af[1][2][2], af[1][2][3], b[j].x, b[j].y);
                        }
                    }
                    #pragma unroll
                    for (int j = 0; j < 4; ++j) {
                        const int ss = 2 * p + 1;
                        mma16816(acc[0][jbg + j], af[0][ss][0], af[0][ss][1], af[0][ss][2], af[0][ss][3], b[j].z, b[j].w);
                        mma16816(acc[1][jbg + j], af[1][ss][0], af[1][ss][1], af[1][ss][2], af[1][ss][3], b[j].z, b[j].w);
                    }
                }
            }
        }

        // ---- output layer: ReLU(h) @ Wo, quad reduction, write 3 f32/row ----
        #pragma unroll
        for (int r = 0; r < 2; ++r) {
            float p0[3] = {0.f, 0.f, 0.f};
            float p1[3] = {0.f, 0.f, 0.f};
            #pragma unroll
            for (int jb = 0; jb < 8; ++jb) {
                float h0 = fmaxf(acc[r][jb][0], 0.0f);
                float h1 = fmaxf(acc[r][jb][1], 0.0f);
                float h2 = fmaxf(acc[r][jb][2], 0.0f);
                float h3 = fmaxf(acc[r][jb][3], 0.0f);
                #pragma unroll
                for (int j = 0; j < 3; ++j) {
                    float2 w = s.wop[t][jb][j];
                    p0[j] = fmaf(h0, w.x, fmaf(h1, w.y, p0[j]));
                    p1[j] = fmaf(h2, w.x, fmaf(h3, w.y, p1[j]));
                }
            }
            #pragma unroll
            for (int j = 0; j < 3; ++j) {
                p0[j] += __shfl_xor_sync(0xffffffffu, p0[j], 1);
                p0[j] += __shfl_xor_sync(0xffffffffu, p0[j], 2);
                p1[j] += __shfl_xor_sync(0xffffffffu, p1[j], 1);
                p1[j] += __shfl_xor_sync(0xffffffffu, p1[j], 2);
            }
            if (t == 0) {
                size_t r0 = rbase + (size_t)r * 16 + g;
                size_t r1 = r0 + 8;
                float* o0 = out + r0 * OUTD;
                float* o1 = out + r1 * OUTD;
                o0[0] = p0[0]; o0[1] = p0[1]; o0[2] = p0[2];
                o1[0] = p1[0]; o1[1] = p1[1]; o1[2] = p1[2];
            }
        }
    }
}

extern "C" void kernel_launch(void* const* d_in, const int* in_sizes, int n_in,
                              void* d_out, int out_size) {
    const float* x  = (const float*)d_in[0];
    const float* W0 = (const float*)d_in[1];
    const float* Wh = (const float*)d_in[2];
    const float* Wo = (const float*)d_in[3];
    float* out = (float*)d_out;

    int sms = 148;
    cudaDeviceGetAttribute(&sms, cudaDevAttrMultiProcessorCount, 0);
    int grid = sms * 2;                 // persistent, 2 CTAs/SM
    if (grid > NTILES) grid = NTILES;

    tcnn_mlp_kernel<<<grid, NTHREADS>>>(x, W0, Wh, Wo, out);
}

// round 5
// speedup vs baseline: 1.7005x; 1.0209x over previous
#include <cuda_runtime.h>
#include <cuda_fp16.h>
#include <cstdint>

// ============================ problem constants ============================
#define BATCHN   2097152
#define IN_DIMS  32
#define HIDDEN   64
#define OUTD     3
#define NMAT     5                 // W0 + 4 hidden (all followed by ReLU)
#define NTHREADS 256               // 8 warps
#define NROWSETS 4
#define ROWS_PER_WARP (16 * NROWSETS)            // 64
#define ROWS_PER_CTA  (8 * ROWS_PER_WARP)        // 512
#define NTILES   (BATCHN / ROWS_PER_CTA)         // 4096

// ============================ SMEM layout ============================
// pkw[l][p][n][t] : uint4 = B fragments for k-step pair p = {ss=2p, ss=2p+1}
// for thread (g,t), column n = jb*8+g:
//   .x = f16x2{ W[32p+2t,    n], W[32p+2t+1,  n] }   (b0 of ss=2p)
//   .y = f16x2{ W[32p+2t+8,  n], W[32p+2t+9,  n] }   (b1 of ss=2p)
//   .z = f16x2{ W[32p+2t+16, n], W[32p+2t+17, n] }   (b0 of ss=2p+1)
//   .w = f16x2{ W[32p+2t+24, n], W[32p+2t+25, n] }   (b1 of ss=2p+1)
// One LDS.128 per (jb, k-step-pair); for fixed jb, lanes (g,t) cover a
// contiguous 512B block in 16B steps -> 4 phases x 128B, conflict-free.
struct Smem {
    uint4  pkw[NMAT][2][64][4];   // 40960 B
    float2 wop[4][8][3];          // 768 B : {Wo[k0,j], Wo[k0+1,j]}, k0=jb*8+2t
};

// ============================ device helpers ============================
__device__ __forceinline__ void mma16816(float* d,
    uint32_t a0, uint32_t a1, uint32_t a2, uint32_t a3,
    uint32_t b0, uint32_t b1)
{
    asm volatile(
        "mma.sync.aligned.m16n8k16.row.col.f32.f16.f16.f32 "
        "{%0,%1,%2,%3}, {%4,%5,%6,%7}, {%8,%9}, {%0,%1,%2,%3};"
        : "+f"(d[0]), "+f"(d[1]), "+f"(d[2]), "+f"(d[3])
        : "r"(a0), "r"(a1), "r"(a2), "r"(a3), "r"(b0), "r"(b1));
}

// D = A*B + 0  (no accumulator zero-init needed)
__device__ __forceinline__ void mma16816_zc(float* d,
    uint32_t a0, uint32_t a1, uint32_t a2, uint32_t a3,
    uint32_t b0, uint32_t b1)
{
    asm volatile(
        "mma.sync.aligned.m16n8k16.row.col.f32.f16.f16.f32 "
        "{%0,%1,%2,%3}, {%4,%5,%6,%7}, {%8,%9}, {%10,%11,%12,%13};"
        : "=f"(d[0]), "=f"(d[1]), "=f"(d[2]), "=f"(d[3])
        : "r"(a0), "r"(a1), "r"(a2), "r"(a3), "r"(b0), "r"(b1),
          "f"(0.0f), "f"(0.0f), "f"(0.0f), "f"(0.0f));
}

// pack two f32 -> f16x2 (first arg = low half)
__device__ __forceinline__ uint32_t pack2(float lo, float hi) {
    uint32_t r;
    asm("cvt.rn.f16x2.f32 %0, %1, %2;" : "=r"(r) : "f"(hi), "f"(lo));
    return r;
}
// fused relu+pack: single cvt.rn.relu.f16x2.f32 (base PTX, sm_80+)
__device__ __forceinline__ uint32_t packrelu(float lo, float hi) {
    uint32_t r;
    asm("cvt.rn.relu.f16x2.f32 %0, %1, %2;" : "=r"(r) : "f"(hi), "f"(lo));
    return r;
}
__device__ __forceinline__ void prefetch_l2(const void* p) {
    asm volatile("prefetch.global.L2 [%0];" :: "l"(p));
}

// ============================ kernel ============================
__global__ void __launch_bounds__(NTHREADS, 1)
tcnn_mlp_kernel(const float* __restrict__ x,
                const float* __restrict__ W0,
                const float* __restrict__ Wh,
                const float* __restrict__ Wo,
                float* __restrict__ out)
{
    __shared__ Smem s;
    const int tid  = threadIdx.x;
    const int warp = tid >> 5;
    const int lane = tid & 31;
    const int g    = lane >> 2;   // groupID
    const int t    = lane & 3;    // threadID in group

    // ---- stage weights once per persistent CTA ----
    for (int idx = tid; idx < NMAT * 2 * 64 * 4; idx += NTHREADS) {
        int l   = idx >> 9;            // /512
        int rem = idx & 511;
        int p   = rem >> 8;
        int n   = (rem >> 2) & 63;
        int tt  = rem & 3;
        int K0  = p * 32 + 2 * tt;
        const float* W = (l == 0) ? W0 : (Wh + (size_t)(l - 1) * HIDDEN * HIDDEN);
        float w[8];
        #pragma unroll
        for (int i = 0; i < 8; ++i) {
            int k = K0 + (i >> 1) * 8 + (i & 1);   // +0,+1,+8,+9,+16,+17,+24,+25
            float v = 0.0f;
            if (l != 0 || k < IN_DIMS) v = W[k * HIDDEN + n];
            w[i] = v;
        }
        uint4 v4;
        v4.x = pack2(w[0], w[1]);
        v4.y = pack2(w[2], w[3]);
        v4.z = pack2(w[4], w[5]);
        v4.w = pack2(w[6], w[7]);
        s.pkw[l][p][n][tt] = v4;
    }
    for (int idx = tid; idx < 4 * 8 * 3; idx += NTHREADS) {
        int tt = idx / 24;
        int jb = (idx / 3) & 7;
        int j  = idx % 3;
        int k0 = jb * 8 + tt * 2;
        s.wop[tt][jb][j] = make_float2(Wo[k0 * OUTD + j], Wo[(k0 + 1) * OUTD + j]);
    }
    __syncthreads();

    // ---- persistent grid-stride over 512-row tiles ----
    for (int tile = blockIdx.x; tile < NTILES; tile += gridDim.x) {
        const size_t rbase = (size_t)tile * ROWS_PER_CTA + (size_t)warp * ROWS_PER_WARP;

        // L2-prefetch next tile's x rows for this warp (no registers held)
        {
            int ntile = tile + gridDim.x;
            if (ntile < NTILES) {
                const size_t nrb = (size_t)ntile * ROWS_PER_CTA + (size_t)warp * ROWS_PER_WARP;
                prefetch_l2(x + (nrb + lane) * IN_DIMS);
                prefetch_l2(x + (nrb + 32 + lane) * IN_DIMS);
            }
        }

        float acc[NROWSETS][8][4];        // [rowset][n-block][c-frag]
        uint32_t af[NROWSETS][4][4];      // [rowset][k-step][a-frag]

        // ---- layer 0: A fragments straight from gmem (K=32 -> k-steps 0,1) ----
        #pragma unroll
        for (int r = 0; r < NROWSETS; ++r) {
            const float* xr0 = x + (rbase + (size_t)r * 16 + g) * IN_DIMS;
            const float* xr1 = xr0 + 8 * IN_DIMS;
            #pragma unroll
            for (int ss = 0; ss < 2; ++ss) {
                float2 v00 = *reinterpret_cast<const float2*>(xr0 + ss * 16 + 2 * t);
                float2 v01 = *reinterpret_cast<const float2*>(xr0 + ss * 16 + 2 * t + 8);
                float2 v10 = *reinterpret_cast<const float2*>(xr1 + ss * 16 + 2 * t);
                float2 v11 = *reinterpret_cast<const float2*>(xr1 + ss * 16 + 2 * t + 8);
                af[r][ss][0] = pack2(v00.x, v00.y);
                af[r][ss][1] = pack2(v10.x, v10.y);
                af[r][ss][2] = pack2(v01.x, v01.y);
                af[r][ss][3] = pack2(v11.x, v11.y);
            }
        }

        // layer 0 mma: k-step pair p=0 only (ss 0,1), first k-step uses C=0
        #pragma unroll
        for (int jbg = 0; jbg < 8; jbg += 4) {
            uint4 b[4];
            #pragma unroll
            for (int j = 0; j < 4; ++j)
                b[j] = s.pkw[0][0][(jbg + j) * 8 + g][t];
            #pragma unroll
            for (int j = 0; j < 4; ++j)
                #pragma unroll
                for (int r = 0; r < NROWSETS; ++r)
                    mma16816_zc(acc[r][jbg + j], af[r][0][0], af[r][0][1], af[r][0][2], af[r][0][3], b[j].x, b[j].y);
            #pragma unroll
            for (int j = 0; j < 4; ++j)
                #pragma unroll
                for (int r = 0; r < NROWSETS; ++r)
                    mma16816(acc[r][jbg + j], af[r][1][0], af[r][1][1], af[r][1][2], af[r][1][3], b[j].z, b[j].w);
        }

        // ---- hidden layers 1..4: acc -> fused relu+pack -> A-frags -> mma ----
        #pragma unroll
        for (int l = 1; l < NMAT; ++l) {
            #pragma unroll
            for (int r = 0; r < NROWSETS; ++r) {
                #pragma unroll
                for (int ss = 0; ss < 4; ++ss) {
                    af[r][ss][0] = packrelu(acc[r][2 * ss    ][0], acc[r][2 * ss    ][1]);
                    af[r][ss][1] = packrelu(acc[r][2 * ss    ][2], acc[r][2 * ss    ][3]);
                    af[r][ss][2] = packrelu(acc[r][2 * ss + 1][0], acc[r][2 * ss + 1][1]);
                    af[r][ss][3] = packrelu(acc[r][2 * ss + 1][2], acc[r][2 * ss + 1][3]);
                }
            }
            #pragma unroll
            for (int p = 0; p < 2; ++p) {
                #pragma unroll
                for (int jbg = 0; jbg < 8; jbg += 4) {
                    uint4 b[4];
                    #pragma unroll
                    for (int j = 0; j < 4; ++j)
                        b[j] = s.pkw[l][p][(jbg + j) * 8 + g][t];
                    #pragma unroll
                    for (int j = 0; j < 4; ++j) {
                        #pragma unroll
                        for (int r = 0; r < NROWSETS; ++r) {
                            if (p == 0)
                                mma16816_zc(acc[r][jbg + j], af[r][0][0], af[r][0][1], af[r][0][2], af[r][0][3], b[j].x, b[j].y);
                            else
                                mma16816(acc[r][jbg + j], af[r][2][0], af[r][2][1], af[r][2][2], af[r][2][3], b[j].x, b[j].y);
                        }
                    }
                    #pragma unroll
                    for (int j = 0; j < 4; ++j) {
                        const int ss = 2 * p + 1;
                        #pragma unroll
                        for (int r = 0; r < NROWSETS; ++r)
                            mma16816(acc[r][jbg + j], af[r][ss][0], af[r][ss][1], af[r][ss][2], af[r][ss][3], b[j].z, b[j].w);
                    }
                }
            }
        }

        // ---- output layer: ReLU(h) @ Wo, quad reduction, write 3 f32/row ----
        #pragma unroll
        for (int r = 0; r < NROWSETS; ++r) {
            float p0[3] = {0.f, 0.f, 0.f};
            float p1[3] = {0.f, 0.f, 0.f};
            #pragma unroll
            for (int jb = 0; jb < 8; ++jb) {
                float h0 = fmaxf(acc[r][jb][0], 0.0f);
                float h1 = fmaxf(acc[r][jb][1], 0.0f);
                float h2 = fmaxf(acc[r][jb][2], 0.0f);
                float h3 = fmaxf(acc[r][jb][3], 0.0f);
                #pragma unroll
                for (int j = 0; j < 3; ++j) {
                    float2 w = s.wop[t][jb][j];
                    p0[j] = fmaf(h0, w.x, fmaf(h1, w.y, p0[j]));
                    p1[j] = fmaf(h2, w.x, fmaf(h3, w.y, p1[j]));
                }
            }
            #pragma unroll
            for (int j = 0; j < 3; ++j) {
                p0[j] += __shfl_xor_sync(0xffffffffu, p0[j], 1);
                p0[j] += __shfl_xor_sync(0xffffffffu, p0[j], 2);
                p1[j] += __shfl_xor_sync(0xffffffffu, p1[j], 1);
                p1[j] += __shfl_xor_sync(0xffffffffu, p1[j], 2);
            }
            if (t == 0) {
                size_t r0 = rbase + (size_t)r * 16 + g;
                size_t r1 = r0 + 8;
                float* o0 = out + r0 * OUTD;
                float* o1 = out + r1 * OUTD;
                o0[0] = p0[0]; o0[1] = p0[1]; o0[2] = p0[2];
                o1[0] = p1[0]; o1[1] = p1[1]; o1[2] = p1[2];
            }
        }
    }
}

extern "C" void kernel_launch(void* const* d_in, const int* in_sizes, int n_in,
                              void* d_out, int out_size) {
    const float* x  = (const float*)d_in[0];
    const float* W0 = (const float*)d_in[1];
    const float* Wh = (const float*)d_in[2];
    const float* Wo = (const float*)d_in[3];
    float* out = (float*)d_out;

    int sms = 148;
    cudaDeviceGetAttribute(&sms, cudaDevAttrMultiProcessorCount, 0);
    int grid = sms;                     // persistent, 1 CTA/SM (regs > 128)
    if (grid > NTILES) grid = NTILES;

    tcnn_mlp_kernel<<<grid, NTHREADS>>>(x, W0, Wh, Wo, out);
}